// round 3
// baseline (speedup 1.0000x reference)
#include <cuda_runtime.h>

// DenseWarpLayer: bilinear warp, N=8, H=512, W=512, C=32 fp32.
// R3: back to the L1-wavefront-optimal R1 mapping (8 threads/pixel, every
// warp-level LDG.128/STG.128 covers 4 full 128B lines), but each thread now
// handles TWO pixels half-a-grid apart, software-pipelined: both flow loads
// issue first, then all 8 gather loads, then compute + 2 streaming stores.
// This overlaps the flow-load latency with the gather latency (the serial
// flow->gather chain was the R1 limiter) and doubles loads-in-flight per SM.

#define N_ 8
#define H_ 512
#define W_ 512
#define C4_ 8            // 32 channels = 8 float4
#define ROW4 (W_ * C4_)  // float4 per image row
#define HALF_PIX (N_ * H_ * W_ / 2)   // 1,048,576

__device__ __forceinline__ long long gather_base(unsigned pix, unsigned c4,
                                                 const float2 fl,
                                                 float& ax, float& ay)
{
    const unsigned w = pix & (W_ - 1);
    const unsigned h = (pix >> 9) & (H_ - 1);
    const unsigned n = pix >> 18;

    const float qy = (float)h - fl.x;
    const float qx = (float)w - fl.y;

    float fyf = floorf(qy);
    float fxf = floorf(qx);
    fyf = fminf(fmaxf(fyf, 0.0f), (float)(H_ - 2));
    fxf = fminf(fmaxf(fxf, 0.0f), (float)(W_ - 2));

    ay = fminf(fmaxf(qy - fyf, 0.0f), 1.0f);
    ax = fminf(fmaxf(qx - fxf, 0.0f), 1.0f);

    return (((long long)n * H_ + (int)fyf) * W_ + (int)fxf) * C4_ + c4;
}

__device__ __forceinline__ float4 bilerp4(const float4 tl, const float4 tr,
                                          const float4 bl, const float4 br,
                                          const float ax, const float ay)
{
    float4 r; float top, bot;
    top = tl.x + ax * (tr.x - tl.x); bot = bl.x + ax * (br.x - bl.x);
    r.x = top + ay * (bot - top);
    top = tl.y + ax * (tr.y - tl.y); bot = bl.y + ax * (br.y - bl.y);
    r.y = top + ay * (bot - top);
    top = tl.z + ax * (tr.z - tl.z); bot = bl.z + ax * (br.z - bl.z);
    r.z = top + ay * (bot - top);
    top = tl.w + ax * (tr.w - tl.w); bot = bl.w + ax * (br.w - bl.w);
    r.w = top + ay * (bot - top);
    return r;
}

__global__ __launch_bounds__(256)
void dense_warp_kernel(const float* __restrict__ image,
                       const float* __restrict__ flow,
                       float* __restrict__ out)
{
    // threads = HALF_PIX * 8 = 8,388,608; each thread: pixel p and p+HALF_PIX
    const unsigned tid = blockIdx.x * 256u + threadIdx.x;
    const unsigned c4   = tid & 7u;
    const unsigned pix0 = tid >> 3;
    const unsigned pix1 = pix0 + HALF_PIX;

    // ---- stage 1: both flow loads in flight together
    const float2* fl2 = reinterpret_cast<const float2*>(flow);
    const float2 fl0 = __ldg(fl2 + pix0);
    const float2 fl1 = __ldg(fl2 + pix1);

    // ---- stage 2: addresses, then all 8 gathers in flight together
    float ax0, ay0, ax1, ay1;
    const long long rb0 = gather_base(pix0, c4, fl0, ax0, ay0);
    const long long rb1 = gather_base(pix1, c4, fl1, ax1, ay1);

    const float4* img4 = reinterpret_cast<const float4*>(image);
    const float4 tl0 = __ldg(img4 + rb0);
    const float4 tr0 = __ldg(img4 + rb0 + C4_);
    const float4 bl0 = __ldg(img4 + rb0 + ROW4);
    const float4 br0 = __ldg(img4 + rb0 + ROW4 + C4_);
    const float4 tl1 = __ldg(img4 + rb1);
    const float4 tr1 = __ldg(img4 + rb1 + C4_);
    const float4 bl1 = __ldg(img4 + rb1 + ROW4);
    const float4 br1 = __ldg(img4 + rb1 + ROW4 + C4_);

    // ---- stage 3: compute + streaming stores (write-once output)
    const float4 r0 = bilerp4(tl0, tr0, bl0, br0, ax0, ay0);
    const float4 r1 = bilerp4(tl1, tr1, bl1, br1, ax1, ay1);

    float4* out4 = reinterpret_cast<float4*>(out);
    __stcs(out4 + (long long)pix0 * C4_ + c4, r0);
    __stcs(out4 + (long long)pix1 * C4_ + c4, r1);
}

extern "C" void kernel_launch(void* const* d_in, const int* in_sizes, int n_in,
                              void* d_out, int out_size)
{
    const float* image = (const float*)d_in[0];
    const float* flow  = (const float*)d_in[1];
    float* out = (float*)d_out;

    // 8,388,608 threads / 256 = 32,768 blocks
    dense_warp_kernel<<<32768, 256>>>(image, flow, out);
}

// round 4
// speedup vs baseline: 1.2060x; 1.2060x over previous
#include <cuda_runtime.h>

// DenseWarpLayer: bilinear warp, N=8, H=512, W=512, C=32 fp32.
// R4: R1's occupancy-optimal mapping (8 threads/pixel, warp-level LDG.128
// covers 4 full 128B lines) with exactly one structural change: each thread
// processes TWO adjacent pixels SEQUENTIALLY, with both flow loads hoisted.
// Peak live registers stay ~30 (only one pixel's 16 gather regs live at a
// time), so we keep 8 blocks/SM (64 warps) while removing one flow-load
// latency from every two-pixel chain. All indexing is 32-bit (max index
// 16.7M < 2^31) to cut ALU and registers vs R1's long long.

#define N_ 8
#define H_ 512
#define W_ 512
#define C4_ 8u            // 32 channels = 8 float4
#define ROW4 (W_ * C4_)   // float4 per image row = 4096

__device__ __forceinline__ unsigned gather_base(unsigned pix, unsigned c4,
                                                const float2 fl,
                                                float& ax, float& ay)
{
    const unsigned w = pix & (W_ - 1);
    const unsigned h = (pix >> 9) & (H_ - 1);
    const unsigned n = pix >> 18;

    const float qy = (float)h - fl.x;
    const float qx = (float)w - fl.y;

    float fyf = floorf(qy);
    float fxf = floorf(qx);
    fyf = fminf(fmaxf(fyf, 0.0f), (float)(H_ - 2));
    fxf = fminf(fmaxf(fxf, 0.0f), (float)(W_ - 2));

    ay = fminf(fmaxf(qy - fyf, 0.0f), 1.0f);
    ax = fminf(fmaxf(qx - fxf, 0.0f), 1.0f);

    return ((n * H_ + (unsigned)(int)fyf) * W_ + (unsigned)(int)fxf) * C4_ + c4;
}

__device__ __forceinline__ float4 bilerp4(const float4 tl, const float4 tr,
                                          const float4 bl, const float4 br,
                                          const float ax, const float ay)
{
    float4 r; float top, bot;
    top = tl.x + ax * (tr.x - tl.x); bot = bl.x + ax * (br.x - bl.x);
    r.x = top + ay * (bot - top);
    top = tl.y + ax * (tr.y - tl.y); bot = bl.y + ax * (br.y - bl.y);
    r.y = top + ay * (bot - top);
    top = tl.z + ax * (tr.z - tl.z); bot = bl.z + ax * (br.z - bl.z);
    r.z = top + ay * (bot - top);
    top = tl.w + ax * (tr.w - tl.w); bot = bl.w + ax * (br.w - bl.w);
    r.w = top + ay * (bot - top);
    return r;
}

__device__ __forceinline__ void do_pixel(const float4* __restrict__ img4,
                                         float4* __restrict__ out4,
                                         unsigned pix, unsigned c4,
                                         const float2 fl)
{
    float ax, ay;
    const unsigned rb = gather_base(pix, c4, fl, ax, ay);

    const float4 tl = __ldg(img4 + rb);
    const float4 tr = __ldg(img4 + rb + C4_);
    const float4 bl = __ldg(img4 + rb + ROW4);
    const float4 br = __ldg(img4 + rb + ROW4 + C4_);

    out4[pix * C4_ + c4] = bilerp4(tl, tr, bl, br, ax, ay);
}

__global__ __launch_bounds__(256, 8)
void dense_warp_kernel(const float* __restrict__ image,
                       const float* __restrict__ flow,
                       float* __restrict__ out)
{
    // threads = N*H*W*8/2 = 8,388,608; each handles pixels pix0 and pix0+4.
    // Warp (32 threads) = 4 pixel-slots x 8 channel-quads; iteration 0 covers
    // pixels [g*8 .. g*8+3], iteration 1 covers [g*8+4 .. g*8+7] -> all
    // warp-level loads/stores remain full-128B-line covered.
    const unsigned tid  = blockIdx.x * 256u + threadIdx.x;
    const unsigned c4   = tid & 7u;
    const unsigned pair = tid >> 3;          // 0 .. 1,048,575
    const unsigned grp  = pair >> 2;
    const unsigned r    = pair & 3u;
    const unsigned pix0 = grp * 8u + r;
    const unsigned pix1 = pix0 + 4u;

    // hoist BOTH flow loads: flow1's latency fully overlaps pixel0's work
    const float2* fl2 = reinterpret_cast<const float2*>(flow);
    const float2 fl0 = __ldg(fl2 + pix0);
    const float2 fl1 = __ldg(fl2 + pix1);

    const float4* img4 = reinterpret_cast<const float4*>(image);
    float4* out4 = reinterpret_cast<float4*>(out);

    do_pixel(img4, out4, pix0, c4, fl0);
    do_pixel(img4, out4, pix1, c4, fl1);
}

extern "C" void kernel_launch(void* const* d_in, const int* in_sizes, int n_in,
                              void* d_out, int out_size)
{
    const float* image = (const float*)d_in[0];
    const float* flow  = (const float*)d_in[1];
    float* out = (float*)d_out;

    // 8,388,608 threads / 256 = 32,768 blocks
    dense_warp_kernel<<<32768, 256>>>(image, flow, out);
}